// round 5
// baseline (speedup 1.0000x reference)
#include <cuda_runtime.h>

#define NB 50000
#define EE 1600000
#define ET (EE + NB)
#define GG 128

// ---------------- device scratch (no allocations allowed) ----------------
__device__ __align__(16) int   g_src[ET];
__device__ __align__(16) int   g_dst[ET];
__device__ __align__(16) int   g_csr[ET];          // src ids sorted by dst
__device__ __align__(16) int   g_deg[NB + 1];
__device__ __align__(16) int   g_off[NB + 1];
__device__ __align__(16) int   g_cur[NB];
__device__ __align__(16) float g_h[NB * 64];       // W-transformed features (per layer)
__device__ __align__(16) float g_act[NB * 64];     // activated layer output / next input
__device__ __align__(16) float g_asrc[NB * 8];
__device__ __align__(16) float g_adst[NB * 8];
__device__ __align__(16) float g_pool[GG * 32];
__device__ __align__(16) float g_cnt[GG];

// ---------------- graph build ----------------
__global__ void k_zero() {
    int i = blockIdx.x * blockDim.x + threadIdx.x;
    if (i <= NB) g_deg[i] = 0;
    if (i < GG * 32) g_pool[i] = 0.f;
    if (i < GG) g_cnt[i] = 0.f;
}

__global__ void k_count(const int* __restrict__ ei) {
    int i = blockIdx.x * blockDim.x + threadIdx.x;
    if (i >= ET) return;
    int s, d;
    if (i < EE) { s = ei[i]; d = ei[EE + i]; }
    else        { s = i - EE; d = s; }
    g_src[i] = s; g_dst[i] = d;
    atomicAdd(&g_deg[d], 1);
}

__global__ void k_scan() {   // 1 block, 1024 threads: exclusive scan of g_deg
    __shared__ int sm[1024];
    const int C = 49;                       // 49*1024 >= NB
    int t = threadIdx.x;
    int start = t * C;
    int end = min(start + C, NB);
    int sum = 0;
    for (int i = start; i < end; i++) sum += g_deg[i];
    sm[t] = sum;
    __syncthreads();
    for (int d = 1; d < 1024; d <<= 1) {
        int v = (t >= d) ? sm[t - d] : 0;
        __syncthreads();
        sm[t] += v;
        __syncthreads();
    }
    int run = (t == 0) ? 0 : sm[t - 1];
    for (int i = start; i < end; i++) {
        g_off[i] = run; g_cur[i] = run;
        run += g_deg[i];
    }
    if (t == 0) g_off[NB] = sm[1023];
}

__global__ void k_scatter() {
    int i = blockIdx.x * blockDim.x + threadIdx.x;
    if (i >= ET) return;
    int d = g_dst[i];
    int pos = atomicAdd(&g_cur[d], 1);
    g_csr[pos] = g_src[i];
}

// ---------------- dense: h = X @ W  (writes g_h) ----------------
// USE_ACT: read input from the device-global g_act instead of the X argument
// (no host-side cudaGetSymbolAddress allowed).
template <int K, int J, bool USE_ACT>
__global__ void k_gemm(const float* __restrict__ Xparam, const float* __restrict__ W) {
    const float* __restrict__ X = USE_ACT ? (const float*)g_act : Xparam;
    constexpr int RB = 32;
    constexpr int CG = J / 4;                 // column groups (4 cols each)
    constexpr int RPT = RB * CG / 256;        // rows per thread (J=64 -> 2, J=32 -> 1)
    __shared__ float sW[K * J];
    __shared__ float sX[RB * K];
    int t = threadIdx.x;
    int row0 = blockIdx.x * RB;
    for (int i = t; i < K * J; i += 256) sW[i] = W[i];
    int nrows = min(RB, NB - row0);
    for (int i = t; i < nrows * K; i += 256) sX[i] = X[(size_t)row0 * K + i];
    __syncthreads();

    int rg = t / CG, cg = t % CG;
    float acc[RPT][4];
#pragma unroll
    for (int r = 0; r < RPT; r++)
#pragma unroll
        for (int q = 0; q < 4; q++) acc[r][q] = 0.f;

#pragma unroll 8
    for (int k = 0; k < K; k++) {
        float xs[RPT];
#pragma unroll
        for (int r = 0; r < RPT; r++) xs[r] = sX[(rg * RPT + r) * K + k];
#pragma unroll
        for (int q = 0; q < 4; q++) {
            float w = sW[k * J + cg + CG * q];
#pragma unroll
            for (int r = 0; r < RPT; r++) acc[r][q] = fmaf(xs[r], w, acc[r][q]);
        }
    }
#pragma unroll
    for (int r = 0; r < RPT; r++) {
        int row = row0 + rg * RPT + r;
        if (row < NB) {
#pragma unroll
            for (int q = 0; q < 4; q++) g_h[(size_t)row * J + cg + CG * q] = acc[r][q];
        }
    }
}

// ---------------- attention coefficients (8 heads x 8 ch) ----------------
__global__ void k_attn(const float* __restrict__ As, const float* __restrict__ Ad) {
    int idx = blockIdx.x * blockDim.x + threadIdx.x;   // n*8 + head
    if (idx >= NB * 8) return;
    int h = idx & 7;
    const float4* hp = (const float4*)(g_h + (size_t)idx * 8);
    float4 v0 = hp[0], v1 = hp[1];
    const float4* ap = (const float4*)(As + h * 8);
    float4 a0 = __ldg(ap), a1 = __ldg(ap + 1);
    const float4* bp = (const float4*)(Ad + h * 8);
    float4 c0 = __ldg(bp), c1 = __ldg(bp + 1);
    g_asrc[idx] = v0.x*a0.x + v0.y*a0.y + v0.z*a0.z + v0.w*a0.w
                + v1.x*a1.x + v1.y*a1.y + v1.z*a1.z + v1.w*a1.w;
    g_adst[idx] = v0.x*c0.x + v0.y*c0.y + v0.z*c0.z + v0.w*c0.w
                + v1.x*c1.x + v1.y*c1.y + v1.z*c1.z + v1.w*c1.w;
}

// ---------------- softmax-aggregate: warp per dst node (8 heads) ----------------
__global__ void k_agg(const float* __restrict__ B) {
    int gw = (blockIdx.x * blockDim.x + threadIdx.x) >> 5;
    if (gw >= NB) return;
    int lane = threadIdx.x & 31;
    int head = lane >> 2;
    int begin = g_off[gw], end = g_off[gw + 1];
    float ad = g_adst[gw * 8 + head];

    float emax = -1e30f;
    for (int i = begin; i < end; i++) {
        int src = __ldg(&g_csr[i]);
        float e = __ldg(&g_asrc[src * 8 + head]) + ad;
        e = (e >= 0.f) ? e : 0.2f * e;
        emax = fmaxf(emax, e);
    }
    float s = 0.f, ax = 0.f, ay = 0.f;
    int j = lane * 2;                              // head*8 + (lane%4)*2 == 2*lane
    for (int i = begin; i < end; i++) {
        int src = __ldg(&g_csr[i]);
        float e = __ldg(&g_asrc[src * 8 + head]) + ad;
        e = (e >= 0.f) ? e : 0.2f * e;
        float p = __expf(e - emax);
        s += p;
        float2 hv = __ldg((const float2*)(g_h + (size_t)src * 64 + j));
        ax = fmaf(p, hv.x, ax);
        ay = fmaf(p, hv.y, ay);
    }
    float inv = 1.f / (s + 1e-16f);
    float ox = ax * inv + B[j];
    float oy = ay * inv + B[j + 1];
    ox = (ox > 0.f) ? ox : (__expf(ox) - 1.f);     // ELU
    oy = (oy > 0.f) ? oy : (__expf(oy) - 1.f);
    *(float2*)(g_act + (size_t)gw * 64 + j) = make_float2(ox, oy);
}

// ---------------- final layer: 1 head, 32 channels ----------------
__global__ void k_attn_final(const float* __restrict__ As, const float* __restrict__ Ad) {
    int n = blockIdx.x * blockDim.x + threadIdx.x;
    if (n >= NB) return;
    const float4* hp = (const float4*)(g_h + (size_t)n * 32);
    float s = 0.f, d = 0.f;
#pragma unroll
    for (int q = 0; q < 8; q++) {
        float4 hv = hp[q];
        float4 av = __ldg((const float4*)As + q);
        float4 dv = __ldg((const float4*)Ad + q);
        s += hv.x*av.x + hv.y*av.y + hv.z*av.z + hv.w*av.w;
        d += hv.x*dv.x + hv.y*dv.y + hv.z*dv.z + hv.w*dv.w;
    }
    g_asrc[n] = s; g_adst[n] = d;
}

__global__ void k_agg_final(const float* __restrict__ Bf) {
    int gw = (blockIdx.x * blockDim.x + threadIdx.x) >> 5;
    if (gw >= NB) return;
    int lane = threadIdx.x & 31;
    int begin = g_off[gw], end = g_off[gw + 1];
    float ad = g_adst[gw];
    float emax = -1e30f;
    for (int i = begin; i < end; i++) {
        float e = __ldg(&g_asrc[__ldg(&g_csr[i])]) + ad;
        e = (e >= 0.f) ? e : 0.2f * e;
        emax = fmaxf(emax, e);
    }
    float s = 0.f, acc = 0.f;
    for (int i = begin; i < end; i++) {
        int src = __ldg(&g_csr[i]);
        float e = __ldg(&g_asrc[src]) + ad;
        e = (e >= 0.f) ? e : 0.2f * e;
        float p = __expf(e - emax);
        s += p;
        acc = fmaf(p, __ldg(&g_h[(size_t)src * 32 + lane]), acc);
    }
    g_act[(size_t)gw * 32 + lane] = acc / (s + 1e-16f) + Bf[lane];
}

// ---------------- pooling + head ----------------
__global__ void k_pool(const int* __restrict__ batch) {
    int idx = blockIdx.x * blockDim.x + threadIdx.x;
    if (idx >= NB * 32) return;
    int n = idx >> 5, c = idx & 31;
    int g = batch[n];
    atomicAdd(&g_pool[g * 32 + c], g_act[idx]);
    if (c == 0) atomicAdd(&g_cnt[g], 1.f);
}

__global__ void k_final(const float* __restrict__ Wl, const float* __restrict__ bl,
                        float* __restrict__ out) {
    int t = blockIdx.x * blockDim.x + threadIdx.x;
    if (t >= GG * 2) return;
    int g = t >> 1, o = t & 1;
    float cnt = fmaxf(g_cnt[g], 1.f);
    float acc = 0.f;
#pragma unroll
    for (int c = 0; c < 32; c++) acc += g_pool[g * 32 + c] * Wl[c * 2 + o];
    out[t] = acc / cnt + bl[o];
}

// ---------------- launcher ----------------
extern "C" void kernel_launch(void* const* d_in, const int* in_sizes, int n_in,
                              void* d_out, int out_size) {
    const float* x     = (const float*)d_in[0];
    const int*   ei    = (const int*)d_in[1];      // int32 (JAX x64 disabled)
    const int*   batch = (const int*)d_in[2];      // int32
    const float* W0 = (const float*)d_in[3];
    const float* as0 = (const float*)d_in[4];
    const float* ad0 = (const float*)d_in[5];
    const float* b0 = (const float*)d_in[6];
    const float* W1 = (const float*)d_in[7];
    const float* as1 = (const float*)d_in[8];
    const float* ad1 = (const float*)d_in[9];
    const float* b1 = (const float*)d_in[10];
    const float* W2 = (const float*)d_in[11];
    const float* as2 = (const float*)d_in[12];
    const float* ad2 = (const float*)d_in[13];
    const float* b2 = (const float*)d_in[14];
    const float* Wf = (const float*)d_in[15];
    const float* asf = (const float*)d_in[16];
    const float* adf = (const float*)d_in[17];
    const float* bf = (const float*)d_in[18];
    const float* Wl = (const float*)d_in[19];
    const float* bl = (const float*)d_in[20];
    float* out = (float*)d_out;

    // graph prep (dst is identical across layers -> one CSR build per launch)
    k_zero<<<(NB + 256) / 256, 256>>>();
    k_count<<<(ET + 255) / 256, 256>>>(ei);
    k_scan<<<1, 1024>>>();
    k_scatter<<<(ET + 255) / 256, 256>>>();

    const int GEMM_GRID = (NB + 31) / 32;
    const int ATTN_GRID = (NB * 8 + 255) / 256;
    const int AGG_GRID  = (NB * 32 + 255) / 256;

    // layer 0: 128 -> 8x8
    k_gemm<128, 64, false><<<GEMM_GRID, 256>>>(x, W0);
    k_attn<<<ATTN_GRID, 256>>>(as0, ad0);
    k_agg<<<AGG_GRID, 256>>>(b0);
    // layer 1
    k_gemm<64, 64, true><<<GEMM_GRID, 256>>>(nullptr, W1);
    k_attn<<<ATTN_GRID, 256>>>(as1, ad1);
    k_agg<<<AGG_GRID, 256>>>(b1);
    // layer 2
    k_gemm<64, 64, true><<<GEMM_GRID, 256>>>(nullptr, W2);
    k_attn<<<ATTN_GRID, 256>>>(as2, ad2);
    k_agg<<<AGG_GRID, 256>>>(b2);
    // final conv: 64 -> 32, 1 head
    k_gemm<64, 32, true><<<GEMM_GRID, 256>>>(nullptr, Wf);
    k_attn_final<<<(NB + 255) / 256, 256>>>(asf, adf);
    k_agg_final<<<AGG_GRID, 256>>>(bf);

    // pool + linear head
    k_pool<<<AGG_GRID, 256>>>(batch);
    k_final<<<1, 256>>>(Wl, bl, out);
}

// round 8
// speedup vs baseline: 1.3107x; 1.3107x over previous
#include <cuda_runtime.h>

#define NB 50000
#define EE 1600000
#define ET (EE + NB)
#define GG 128

// ---------------- device scratch (no allocations allowed) ----------------
__device__ __align__(16) int   g_csr[ET];          // src ids sorted by dst
__device__ __align__(16) int   g_deg[NB + 1];
__device__ __align__(16) int   g_off[NB + 1];
__device__ __align__(16) int   g_cur[NB];
__device__ __align__(16) float g_h[NB * 64];       // W-transformed features (per layer)
__device__ __align__(16) float g_act[NB * 64];     // activated layer output / next input
__device__ __align__(16) float g_asrc[NB * 8];
__device__ __align__(16) float g_adst[NB * 8];
__device__ __align__(16) float g_pool[GG * 32];
__device__ __align__(16) float g_cnt[GG];

// ---------------- graph build ----------------
__global__ void k_zero() {
    int i = blockIdx.x * blockDim.x + threadIdx.x;
    if (i <= NB) g_deg[i] = 0;
    if (i < GG * 32) g_pool[i] = 0.f;
    if (i < GG) g_cnt[i] = 0.f;
}

__global__ void k_count(const int* __restrict__ ei) {
    int i = blockIdx.x * blockDim.x + threadIdx.x;
    if (i >= ET) return;
    int d = (i < EE) ? ei[EE + i] : (i - EE);
    atomicAdd(&g_deg[d], 1);
}

__global__ void k_scan() {   // 1 block, 1024 threads: exclusive scan of g_deg
    __shared__ int sm[1024];
    const int C = 49;                       // 49*1024 >= NB
    int t = threadIdx.x;
    int start = t * C;
    int end = min(start + C, NB);
    int sum = 0;
    for (int i = start; i < end; i++) sum += g_deg[i];
    sm[t] = sum;
    __syncthreads();
    for (int d = 1; d < 1024; d <<= 1) {
        int v = (t >= d) ? sm[t - d] : 0;
        __syncthreads();
        sm[t] += v;
        __syncthreads();
    }
    int run = (t == 0) ? 0 : sm[t - 1];
    for (int i = start; i < end; i++) {
        g_off[i] = run; g_cur[i] = run;
        run += g_deg[i];
    }
    if (t == 0) g_off[NB] = sm[1023];
}

__global__ void k_scatter(const int* __restrict__ ei) {
    int i = blockIdx.x * blockDim.x + threadIdx.x;
    if (i >= ET) return;
    int s, d;
    if (i < EE) { s = ei[i]; d = ei[EE + i]; }
    else        { s = i - EE; d = s; }
    int pos = atomicAdd(&g_cur[d], 1);
    g_csr[pos] = s;
}

// ---------------- dense: h = X @ W  (writes g_h) ----------------
// USE_ACT: read input from the device-global g_act instead of the X argument.
template <int K, int J, int RB, bool USE_ACT>
__global__ void k_gemm(const float* __restrict__ Xparam, const float* __restrict__ W) {
    const float* __restrict__ X = USE_ACT ? (const float*)g_act : Xparam;
    constexpr int CG = J / 4;                 // column groups (4 cols each)
    constexpr int RPT = RB * CG / 256;        // rows per thread
    __shared__ float sW[K * J];
    __shared__ float sX[RB * K];
    int t = threadIdx.x;
    int row0 = blockIdx.x * RB;
    for (int i = t; i < K * J; i += 256) sW[i] = W[i];
    int nrows = min(RB, NB - row0);
    for (int i = t; i < nrows * K; i += 256) sX[i] = X[(size_t)row0 * K + i];
    __syncthreads();

    int rg = t / CG, cg = t % CG;
    float acc[RPT][4];
#pragma unroll
    for (int r = 0; r < RPT; r++)
#pragma unroll
        for (int q = 0; q < 4; q++) acc[r][q] = 0.f;

#pragma unroll 8
    for (int k = 0; k < K; k++) {
        float xs[RPT];
#pragma unroll
        for (int r = 0; r < RPT; r++) xs[r] = sX[(rg * RPT + r) * K + k];
#pragma unroll
        for (int q = 0; q < 4; q++) {
            float w = sW[k * J + cg + CG * q];
#pragma unroll
            for (int r = 0; r < RPT; r++) acc[r][q] = fmaf(xs[r], w, acc[r][q]);
        }
    }
#pragma unroll
    for (int r = 0; r < RPT; r++) {
        int row = row0 + rg * RPT + r;
        if (row < NB) {
#pragma unroll
            for (int q = 0; q < 4; q++) g_h[(size_t)row * J + cg + CG * q] = acc[r][q];
        }
    }
}

// ---------------- attention coefficients (8 heads x 8 ch) ----------------
__global__ void k_attn(const float* __restrict__ As, const float* __restrict__ Ad) {
    int idx = blockIdx.x * blockDim.x + threadIdx.x;   // n*8 + head
    if (idx >= NB * 8) return;
    int h = idx & 7;
    const float4* hp = (const float4*)(g_h + (size_t)idx * 8);
    float4 v0 = hp[0], v1 = hp[1];
    const float4* ap = (const float4*)(As + h * 8);
    float4 a0 = __ldg(ap), a1 = __ldg(ap + 1);
    const float4* bp = (const float4*)(Ad + h * 8);
    float4 c0 = __ldg(bp), c1 = __ldg(bp + 1);
    g_asrc[idx] = v0.x*a0.x + v0.y*a0.y + v0.z*a0.z + v0.w*a0.w
                + v1.x*a1.x + v1.y*a1.y + v1.z*a1.z + v1.w*a1.w;
    g_adst[idx] = v0.x*c0.x + v0.y*c0.y + v0.z*c0.z + v0.w*c0.w
                + v1.x*c1.x + v1.y*c1.y + v1.z*c1.z + v1.w*c1.w;
}

// ---------------- softmax-aggregate: warp per dst node, single pass ----------------
// exp(e)/sum(exp(e)) == exp(e-max)/sum(exp(e-max)); |e| is O(10) here so no
// overflow (clamped at 80 as a guard: exp(80)*deg < fp32 max).
__global__ void k_agg(const float* __restrict__ B) {
    int gw = (blockIdx.x * blockDim.x + threadIdx.x) >> 5;
    if (gw >= NB) return;
    int lane = threadIdx.x & 31;
    int head = lane >> 2;
    int begin = g_off[gw], end = g_off[gw + 1];
    float ad = g_adst[gw * 8 + head];
    int j = lane * 2;                              // head*8 + (lane%4)*2 == 2*lane

    float s = 0.f, ax = 0.f, ay = 0.f;
    for (int i = begin; i < end; i++) {
        int src = __ldg(&g_csr[i]);
        float e = __ldg(&g_asrc[src * 8 + head]) + ad;
        e = (e >= 0.f) ? e : 0.2f * e;
        float p = __expf(fminf(e, 80.f));
        float2 hv = __ldg((const float2*)(g_h + (size_t)src * 64 + j));
        s += p;
        ax = fmaf(p, hv.x, ax);
        ay = fmaf(p, hv.y, ay);
    }
    float inv = 1.f / (s + 1e-16f);
    float ox = ax * inv + B[j];
    float oy = ay * inv + B[j + 1];
    ox = (ox > 0.f) ? ox : (__expf(ox) - 1.f);     // ELU
    oy = (oy > 0.f) ? oy : (__expf(oy) - 1.f);
    *(float2*)(g_act + (size_t)gw * 64 + j) = make_float2(ox, oy);
}

// ---------------- final layer: 1 head, 32 channels ----------------
__global__ void k_attn_final(const float* __restrict__ As, const float* __restrict__ Ad) {
    int n = blockIdx.x * blockDim.x + threadIdx.x;
    if (n >= NB) return;
    const float4* hp = (const float4*)(g_h + (size_t)n * 32);
    float s = 0.f, d = 0.f;
#pragma unroll
    for (int q = 0; q < 8; q++) {
        float4 hv = hp[q];
        float4 av = __ldg((const float4*)As + q);
        float4 dv = __ldg((const float4*)Ad + q);
        s += hv.x*av.x + hv.y*av.y + hv.z*av.z + hv.w*av.w;
        d += hv.x*dv.x + hv.y*dv.y + hv.z*dv.z + hv.w*dv.w;
    }
    g_asrc[n] = s; g_adst[n] = d;
}

// single pass + fused global mean-pool accumulation
__global__ void k_agg_final(const float* __restrict__ Bf, const int* __restrict__ batch) {
    int gw = (blockIdx.x * blockDim.x + threadIdx.x) >> 5;
    if (gw >= NB) return;
    int lane = threadIdx.x & 31;
    int begin = g_off[gw], end = g_off[gw + 1];
    float ad = g_adst[gw];

    float s = 0.f, acc = 0.f;
    for (int i = begin; i < end; i++) {
        int src = __ldg(&g_csr[i]);
        float e = __ldg(&g_asrc[src]) + ad;
        e = (e >= 0.f) ? e : 0.2f * e;
        float p = __expf(fminf(e, 80.f));
        s += p;
        acc = fmaf(p, __ldg(&g_h[(size_t)src * 32 + lane]), acc);
    }
    float o = acc / (s + 1e-16f) + Bf[lane];
    int g = batch[gw];
    atomicAdd(&g_pool[g * 32 + lane], o);
    if (lane == 0) atomicAdd(&g_cnt[g], 1.f);
}

// ---------------- head ----------------
__global__ void k_final(const float* __restrict__ Wl, const float* __restrict__ bl,
                        float* __restrict__ out) {
    int t = blockIdx.x * blockDim.x + threadIdx.x;
    if (t >= GG * 2) return;
    int g = t >> 1, o = t & 1;
    float cnt = fmaxf(g_cnt[g], 1.f);
    float acc = 0.f;
#pragma unroll
    for (int c = 0; c < 32; c++) acc += g_pool[g * 32 + c] * Wl[c * 2 + o];
    out[t] = acc / cnt + bl[o];
}

// ---------------- launcher ----------------
extern "C" void kernel_launch(void* const* d_in, const int* in_sizes, int n_in,
                              void* d_out, int out_size) {
    const float* x     = (const float*)d_in[0];
    const int*   ei    = (const int*)d_in[1];      // int32
    const int*   batch = (const int*)d_in[2];      // int32
    const float* W0 = (const float*)d_in[3];
    const float* as0 = (const float*)d_in[4];
    const float* ad0 = (const float*)d_in[5];
    const float* b0 = (const float*)d_in[6];
    const float* W1 = (const float*)d_in[7];
    const float* as1 = (const float*)d_in[8];
    const float* ad1 = (const float*)d_in[9];
    const float* b1 = (const float*)d_in[10];
    const float* W2 = (const float*)d_in[11];
    const float* as2 = (const float*)d_in[12];
    const float* ad2 = (const float*)d_in[13];
    const float* b2 = (const float*)d_in[14];
    const float* Wf = (const float*)d_in[15];
    const float* asf = (const float*)d_in[16];
    const float* adf = (const float*)d_in[17];
    const float* bf = (const float*)d_in[18];
    const float* Wl = (const float*)d_in[19];
    const float* bl = (const float*)d_in[20];
    float* out = (float*)d_out;

    // graph prep (dst is identical across layers -> one CSR build per launch)
    k_zero<<<(NB + 256) / 256, 256>>>();
    k_count<<<(ET + 255) / 256, 256>>>(ei);
    k_scan<<<1, 1024>>>();
    k_scatter<<<(ET + 255) / 256, 256>>>(ei);

    const int ATTN_GRID = (NB * 8 + 255) / 256;
    const int AGG_GRID  = (NB * 32 + 255) / 256;

    // layer 0: 128 -> 8x8   (RB=32: 48KB smem)
    k_gemm<128, 64, 32, false><<<(NB + 31) / 32, 256>>>(x, W0);
    k_attn<<<ATTN_GRID, 256>>>(as0, ad0);
    k_agg<<<AGG_GRID, 256>>>(b0);
    // layer 1  (RB=64: 32KB smem, 4x4 register blocking)
    k_gemm<64, 64, 64, true><<<(NB + 63) / 64, 256>>>(nullptr, W1);
    k_attn<<<ATTN_GRID, 256>>>(as1, ad1);
    k_agg<<<AGG_GRID, 256>>>(b1);
    // layer 2
    k_gemm<64, 64, 64, true><<<(NB + 63) / 64, 256>>>(nullptr, W2);
    k_attn<<<ATTN_GRID, 256>>>(as2, ad2);
    k_agg<<<AGG_GRID, 256>>>(b2);
    // final conv: 64 -> 32, 1 head
    k_gemm<64, 32, 64, true><<<(NB + 63) / 64, 256>>>(nullptr, Wf);
    k_attn_final<<<(NB + 255) / 256, 256>>>(asf, adf);
    k_agg_final<<<AGG_GRID, 256>>>(bf, batch);

    // linear head
    k_final<<<1, 256>>>(Wl, bl, out);
}